// round 16
// baseline (speedup 1.0000x reference)
#include <cuda_runtime.h>

// VectorQuantizer: z [32768, 64] fp32, codebook [1024, 64] fp32.
// Outputs (float32, concatenated): z_q (2097152) | loss (1) | indices (32768).
//
// d2_k = fl( fl(znorm + cnorm_k) - fl(2 * dot_k) )  -- replicates reference
// rounding composition so argmin matches jnp.argmin (first-min tie-break).
//
// R16: evidence (vq ncu: L1=75.6% > fma=47.6%) says the k-loop LDS traffic
// binds, fma pipe half idle. Widen thread tile 4x4 -> 4 rows x 8 codes:
// per k = 1 LDS.128(z) + 2 LDS.128(c) + 8 pack + 16 FFMA2, halving LDS
// per FMA. 128-thread blocks (tx=tid&7 codes, ty=tid>>3 rows), occ 6.
// Per-dot fma.rn chains, epilogue, tie-break order all bit-identical.

#define NROWS    32768
#define DIM      64
#define KCODES   1024
#define TM       64          // rows per block
#define TN       64          // codes per tile
#define NTILES   (KCODES / TN)
#define NTHREADS 128
#define NBLOCKS  (NROWS / TM)
#define ZS       68          // smem stride (floats), mult of 4 for float4 align
#define CS       68

typedef unsigned long long ull;

__device__ __align__(16) float g_cnorm[KCODES];
__device__ __align__(16) float g_cbT[DIM * KCODES];   // transposed codebook
__device__ ull          g_loss_acc = 0ULL;   // fixed-point sum, 2^20 scale
__device__ unsigned int g_ticket   = 0u;     // completion ticket

__device__ __forceinline__ ull pack2dup(float x) {
    ull r; asm("mov.b64 %0, {%1, %1};" : "=l"(r) : "f"(x)); return r;
}
__device__ __forceinline__ void fma2(ull& acc, ull a, ull b) {
    asm("fma.rn.f32x2 %0, %1, %2, %0;" : "+l"(acc) : "l"(a), "l"(b));
}
__device__ __forceinline__ void unpack2(ull v, float& lo, float& hi) {
    asm("mov.b64 {%0, %1}, %2;" : "=f"(lo), "=f"(hi) : "l"(v));
}

// ---------------------------------------------------------------------------
// Kernel 1: codebook row norms + global transpose (verified version).
// ---------------------------------------------------------------------------
__global__ void cnorm_kernel(const float* __restrict__ cb) {
    int k = blockIdx.x * 64 + threadIdx.x;
    const float4* row = (const float4*)(cb + k * DIM);
    float4 v[16];
#pragma unroll
    for (int i = 0; i < 16; i++) v[i] = __ldg(row + i);
    float s = 0.0f;
#pragma unroll
    for (int i = 0; i < 16; i++) {
        s = __fadd_rn(s, __fmul_rn(v[i].x, v[i].x));
        s = __fadd_rn(s, __fmul_rn(v[i].y, v[i].y));
        s = __fadd_rn(s, __fmul_rn(v[i].z, v[i].z));
        s = __fadd_rn(s, __fmul_rn(v[i].w, v[i].w));
    }
    g_cnorm[k] = s;
#pragma unroll
    for (int i = 0; i < 16; i++) {
        g_cbT[(4 * i + 0) * KCODES + k] = v[i].x;
        g_cbT[(4 * i + 1) * KCODES + k] = v[i].y;
        g_cbT[(4 * i + 2) * KCODES + k] = v[i].z;
        g_cbT[(4 * i + 3) * KCODES + k] = v[i].w;
    }
}

// ---------------------------------------------------------------------------
// Kernel 2: main VQ. Block = 64 rows x 1024 codes (16 tiles of 64).
// Thread (tx, ty): tx = tid&7 -> codes {tile*64 + tx*8 + 0..7},
//                  ty = tid>>3 -> rows ty*4..ty*4+3.
// k-loop: z native row-pairs {r0,r1},{r2,r3} (1 LDS.128, 4 distinct/warp);
// c contiguous float4 x2 (conflict-light), dup'd via pack2dup; 16 FFMA2.
// Tail: deterministic fixed-point loss atomic + ticket finalizer.
// ---------------------------------------------------------------------------
__global__ __launch_bounds__(NTHREADS, 6)
void vq_kernel(const float* __restrict__ z,
               const float* __restrict__ codebook,
               float* __restrict__ out) {
    __shared__ float zsT[DIM * ZS];     // zsT[d][r]
    __shared__ float csT[DIM * CS];     // csT[d][c_local]
    __shared__ float znorm_s[TM];
    __shared__ int   ridx_s[TM];
    __shared__ float lsum_s[16];

    const int tid = threadIdx.x;
    const int tx = tid & 7;             // code group (8 codes each)
    const int ty = tid >> 3;            // row group (0..15, 4 rows each)
    const int rowBase = blockIdx.x * TM;

    // ---- load z tile (coalesced float4), store transposed ----
    {
        const float4* zsrc = (const float4*)(z + rowBase * DIM);
        #pragma unroll
        for (int i = 0; i < 8; i++) {
            int flat4 = i * NTHREADS + tid;      // 64 rows x 16 quads
            int r = flat4 >> 4, q = flat4 & 15;
            float4 v = zsrc[flat4];
            zsT[(q * 4 + 0) * ZS + r] = v.x;
            zsT[(q * 4 + 1) * ZS + r] = v.y;
            zsT[(q * 4 + 2) * ZS + r] = v.z;
            zsT[(q * 4 + 3) * ZS + r] = v.w;
        }
    }
    __syncthreads();

    // ---- row norms: square (rounded) then sequential add, ascending d ----
    if (tid < TM) {
        float s = 0.0f;
        #pragma unroll
        for (int k = 0; k < DIM; k++) {
            float v = zsT[k * ZS + tid];
            s = __fadd_rn(s, __fmul_rn(v, v));
        }
        znorm_s[tid] = s;
    }
    __syncthreads();

    float zn[4];
    #pragma unroll
    for (int r = 0; r < 4; r++) zn[r] = znorm_s[(ty << 2) + r];

    float minval[4] = {3.4e38f, 3.4e38f, 3.4e38f, 3.4e38f};
    int   minidx[4] = {0, 0, 0, 0};

    for (int t = 0; t < NTILES; t++) {
        const int cbase = t * TN;

        // ---- load code tile from g_cbT: coalesced float4 LDG + float4 STS,
        //      conflict-free (contiguous within each dim row) ----
        {
            const float4* src = (const float4*)(g_cbT + cbase);
            #pragma unroll
            for (int it = 0; it < 8; it++) {
                int flat4 = it * NTHREADS + tid;     // 64 dims x 16 quads
                int d = flat4 >> 4, j = flat4 & 15;
                float4 v = __ldg(src + d * (KCODES / 4) + j);
                *(float4*)(csT + d * CS + 4 * j) = v;
            }
        }
        __syncthreads();

        // acc[rp][c]: rp=0 -> rows (0,1) packed, rp=1 -> rows (2,3) packed
        ull acc[2][8];
        #pragma unroll
        for (int rp = 0; rp < 2; rp++)
            #pragma unroll
            for (int c = 0; c < 8; c++) acc[rp][c] = 0ull;  // {0.f, 0.f}

        #pragma unroll 8
        for (int k = 0; k < DIM; k++) {
            const ull* zp = (const ull*)&zsT[k * ZS + (ty << 2)];
            ull z01 = zp[0];           // {z[row0], z[row1]}
            ull z23 = zp[1];           // {z[row2], z[row3]}
            const float4* cp4 = (const float4*)&csT[k * CS + (tx << 3)];
            float4 cva = cp4[0];       // c0..c3
            float4 cvb = cp4[1];       // c4..c7
            ull c0 = pack2dup(cva.x);
            ull c1 = pack2dup(cva.y);
            ull c2 = pack2dup(cva.z);
            ull c3 = pack2dup(cva.w);
            ull c4 = pack2dup(cvb.x);
            ull c5 = pack2dup(cvb.y);
            ull c6 = pack2dup(cvb.z);
            ull c7 = pack2dup(cvb.w);
            fma2(acc[0][0], z01, c0); fma2(acc[1][0], z23, c0);
            fma2(acc[0][1], z01, c1); fma2(acc[1][1], z23, c1);
            fma2(acc[0][2], z01, c2); fma2(acc[1][2], z23, c2);
            fma2(acc[0][3], z01, c3); fma2(acc[1][3], z23, c3);
            fma2(acc[0][4], z01, c4); fma2(acc[1][4], z23, c4);
            fma2(acc[0][5], z01, c5); fma2(acc[1][5], z23, c5);
            fma2(acc[0][6], z01, c6); fma2(acc[1][6], z23, c6);
            fma2(acc[0][7], z01, c7); fma2(acc[1][7], z23, c7);
        }

        // epilogue: dist = fl( fl(znorm + cnorm) - fl(2*dot) ), codes ascending
        const float4* cnp = (const float4*)(g_cnorm + cbase + (tx << 3));
        float4 cn4a = cnp[0], cn4b = cnp[1];
        float cna[8] = {cn4a.x, cn4a.y, cn4a.z, cn4a.w,
                        cn4b.x, cn4b.y, cn4b.z, cn4b.w};
        #pragma unroll
        for (int c = 0; c < 8; c++) {
            int code = cbase + (tx << 3) + c;
            #pragma unroll
            for (int rp = 0; rp < 2; rp++) {
                float dlo, dhi;
                unpack2(acc[rp][c], dlo, dhi);
                int r0 = rp * 2, r1 = rp * 2 + 1;
                float t0 = __fadd_rn(zn[r0], cna[c]);
                float d0 = __fsub_rn(t0, __fmul_rn(2.0f, dlo));
                if (d0 < minval[r0]) { minval[r0] = d0; minidx[r0] = code; }
                float t1 = __fadd_rn(zn[r1], cna[c]);
                float d1 = __fsub_rn(t1, __fmul_rn(2.0f, dhi));
                if (d1 < minval[r1]) { minval[r1] = d1; minidx[r1] = code; }
            }
        }
        __syncthreads();
    }

    // ---- cross-lane reduction over the 8 code-lanes (same ty group) ----
    #pragma unroll
    for (int r = 0; r < 4; r++) {
        #pragma unroll
        for (int m = 4; m >= 1; m >>= 1) {
            float ov = __shfl_xor_sync(0xffffffffu, minval[r], m);
            int   oi = __shfl_xor_sync(0xffffffffu, minidx[r], m);
            if (ov < minval[r] || (ov == minval[r] && oi < minidx[r])) {
                minval[r] = ov; minidx[r] = oi;
            }
        }
    }

    if (tx == 0) {
        float s = 0.0f;
        #pragma unroll
        for (int r = 0; r < 4; r++) {
            ridx_s[(ty << 2) + r] = minidx[r];
            s = __fadd_rn(s, minval[r]);   // = ||z_r - c_idx||^2
        }
        lsum_s[ty] = s;
    }
    __syncthreads();

    // ---- fused loss: deterministic fixed-point atomic + ticket finalize ----
    if (tid == 0) {
        float s = 0.0f;
        #pragma unroll
        for (int i = 0; i < 16; i++) s = __fadd_rn(s, lsum_s[i]);
        ull q = (ull)__double2ll_rn((double)s * 1048576.0);
        atomicAdd(&g_loss_acc, q);
        __threadfence();
        unsigned int ticket = atomicAdd(&g_ticket, 1u);
        if (ticket == NBLOCKS - 1) {
            ull tot = atomicAdd(&g_loss_acc, 0ULL);   // coherent read
            double sum = (double)tot * (1.0 / 1048576.0);
            float mean = (float)(sum / (double)(NROWS * DIM));
            out[NROWS * DIM] = __fadd_rn(mean, __fmul_rn(0.25f, mean));
            g_loss_acc = 0ULL;     // reset for next graph replay
            g_ticket   = 0u;
            __threadfence();
        }
    }

    // ---- write indices (as float) ----
    if (tid < TM) {
        out[NROWS * DIM + 1 + rowBase + tid] = (float)ridx_s[tid];
    }

    // ---- write z_q = codebook[idx] (coalesced) ----
    #pragma unroll
    for (int i = 0; i < 32; i++) {
        int flat = i * NTHREADS + tid;
        int r = flat >> 6, c = flat & 63;
        out[(rowBase + r) * DIM + c] = codebook[ridx_s[r] * DIM + c];
    }
}

extern "C" void kernel_launch(void* const* d_in, const int* in_sizes, int n_in,
                              void* d_out, int out_size) {
    const float* z        = (const float*)d_in[0];
    const float* codebook = (const float*)d_in[1];
    float* out = (float*)d_out;

    cnorm_kernel<<<KCODES / 64, 64>>>(codebook);
    vq_kernel<<<NBLOCKS, NTHREADS>>>(z, codebook, out);
}

// round 17
// speedup vs baseline: 1.3382x; 1.3382x over previous
#include <cuda_runtime.h>

// VectorQuantizer: z [32768, 64] fp32, codebook [1024, 64] fp32.
// Outputs (float32, concatenated): z_q (2097152) | loss (1) | indices (32768).
//
// d2_k = fl( fl(znorm + cnorm_k) - fl(2 * dot_k) )  -- replicates reference
// rounding composition so argmin matches jnp.argmin (first-min tie-break).
//
// R17: k-loop is L1TEX-wavefront-bound (R15: L1=75.6% > fma=47.6%).
// Wavefronts/k/warp = distinct bytes touched; reshape the WARP footprint to
// 16 rows x 32 codes (was 8 x 64): z 64B (1 wf) + c 128B (1 wf) = 2 wf/k
// vs 3. Thread tile stays 4x4; R4 instruction body unchanged. Each warp
// scans half the codes; exact first-min restored by a lexicographic (val,idx)
// combine across warp pairs in smem. ZS=96/CS=64 + 128B alignment make both
// k-loop reads line-aligned. Occ 4, prefetch retained.

#define NROWS    32768
#define DIM      64
#define KCODES   1024
#define TM       64          // rows per block
#define TN       64          // codes per tile
#define NTILES   (KCODES / TN)
#define NTHREADS 256
#define NBLOCKS  (NROWS / TM)
#define ZS       96          // float stride: 384B = 3 lines -> z reads aligned
#define CS       64          // float stride: 256B -> c half-tiles line-aligned

typedef unsigned long long ull;

__device__ __align__(16) float g_cnorm[KCODES];
__device__ __align__(16) float g_cbT[DIM * KCODES];   // transposed codebook
__device__ ull          g_loss_acc = 0ULL;   // fixed-point sum, 2^20 scale
__device__ unsigned int g_ticket   = 0u;     // completion ticket

__device__ __forceinline__ ull pack2dup(float x) {
    ull r; asm("mov.b64 %0, {%1, %1};" : "=l"(r) : "f"(x)); return r;
}
__device__ __forceinline__ void fma2(ull& acc, ull a, ull b) {
    asm("fma.rn.f32x2 %0, %1, %2, %0;" : "+l"(acc) : "l"(a), "l"(b));
}
__device__ __forceinline__ void unpack2(ull v, float& lo, float& hi) {
    asm("mov.b64 {%0, %1}, %2;" : "=f"(lo), "=f"(hi) : "l"(v));
}

// ---------------------------------------------------------------------------
// Kernel 1: codebook row norms + global transpose (verified version).
// ---------------------------------------------------------------------------
__global__ void cnorm_kernel(const float* __restrict__ cb) {
    int k = blockIdx.x * 64 + threadIdx.x;
    const float4* row = (const float4*)(cb + k * DIM);
    float4 v[16];
#pragma unroll
    for (int i = 0; i < 16; i++) v[i] = __ldg(row + i);
    float s = 0.0f;
#pragma unroll
    for (int i = 0; i < 16; i++) {
        s = __fadd_rn(s, __fmul_rn(v[i].x, v[i].x));
        s = __fadd_rn(s, __fmul_rn(v[i].y, v[i].y));
        s = __fadd_rn(s, __fmul_rn(v[i].z, v[i].z));
        s = __fadd_rn(s, __fmul_rn(v[i].w, v[i].w));
    }
    g_cnorm[k] = s;
#pragma unroll
    for (int i = 0; i < 16; i++) {
        g_cbT[(4 * i + 0) * KCODES + k] = v[i].x;
        g_cbT[(4 * i + 1) * KCODES + k] = v[i].y;
        g_cbT[(4 * i + 2) * KCODES + k] = v[i].z;
        g_cbT[(4 * i + 3) * KCODES + k] = v[i].w;
    }
}

// ---------------------------------------------------------------------------
// Kernel 2: main VQ. Block = 64 rows x 1024 codes (16 tiles of 64).
// Warp w (0..7): rows (w>>1)*16 + tyl*4 (tyl = lane>>3), codes
// (w&1)*32 + txl*4 (txl = lane&7) within each tile. Thread tile 4x4,
// R4 f32x2 body. k-loop: 1 LDS.128 z (64B/warp, aligned) + 1 LDS.128 c
// (128B/warp, aligned) -> 2 wavefronts per warp-k.
// Tail: cross-half lexicographic argmin combine; fixed-point loss atomic.
// ---------------------------------------------------------------------------
__global__ __launch_bounds__(NTHREADS, 4)
void vq_kernel(const float* __restrict__ z,
               const float* __restrict__ codebook,
               float* __restrict__ out) {
    __shared__ __align__(128) float zsT[DIM * ZS];   // zsT[d][r]
    __shared__ __align__(128) float csT[DIM * CS];   // csT[d][c_local]
    __shared__ float znorm_s[TM];
    __shared__ int   ridx_s[TM];
    __shared__ float mv_s[2][TM];
    __shared__ int   mi_s[2][TM];
    __shared__ float lsum_v[TM];

    const int tid = threadIdx.x;
    const int lane = tid & 31;
    const int wid  = tid >> 5;
    const int txl = lane & 7;           // code quad within half
    const int tyl = lane >> 3;          // row quad within warp slice
    const int chalf = wid & 1;          // code half (0: 0..31, 1: 32..63)
    const int rbase = (wid >> 1) * 16 + tyl * 4;   // first of 4 rows
    const int cloc  = chalf * 32 + txl * 4;        // first of 4 local codes
    const int rowBase = blockIdx.x * TM;

    // loader coordinates (R15 pattern): thread owns code-quad jj of dims 16p+dg
    const int jj = tid & 15;
    const int dg = tid >> 4;

    // ---- load z tile (coalesced float4), store transposed ----
    {
        const float4* zsrc = (const float4*)(z + rowBase * DIM);
        #pragma unroll
        for (int i = 0; i < 4; i++) {
            int flat4 = i * NTHREADS + tid;      // 64 rows x 16 quads
            int r = flat4 >> 4, q = flat4 & 15;
            float4 v = zsrc[flat4];
            zsT[(q * 4 + 0) * ZS + r] = v.x;
            zsT[(q * 4 + 1) * ZS + r] = v.y;
            zsT[(q * 4 + 2) * ZS + r] = v.z;
            zsT[(q * 4 + 3) * ZS + r] = v.w;
        }
    }

    // ---- prefetch code tile 0 (transposed rows, coalesced float4) ----
    float4 pf[4];
    #pragma unroll
    for (int p = 0; p < 4; p++)
        pf[p] = __ldg((const float4*)(g_cbT + (p * 16 + dg) * KCODES) + jj);

    __syncthreads();

    // ---- row norms: square (rounded) then sequential add, ascending d ----
    if (tid < TM) {
        float s = 0.0f;
        #pragma unroll
        for (int k = 0; k < DIM; k++) {
            float v = zsT[k * ZS + tid];
            s = __fadd_rn(s, __fmul_rn(v, v));
        }
        znorm_s[tid] = s;
    }
    __syncthreads();

    float zn[4];
    #pragma unroll
    for (int r = 0; r < 4; r++) zn[r] = znorm_s[rbase + r];

    float minval[4] = {3.4e38f, 3.4e38f, 3.4e38f, 3.4e38f};
    int   minidx[4] = {0, 0, 0, 0};

    for (int t = 0; t < NTILES; t++) {
        const int cbase = t * TN;

        // ---- store prefetched tile: float4 STS into csT[d][cl] ----
        #pragma unroll
        for (int p = 0; p < 4; p++)
            *(float4*)(csT + (p * 16 + dg) * CS + 4 * jj) = pf[p];
        __syncthreads();

        // ---- issue next tile's loads; consumed after the k-loop ----
        if (t + 1 < NTILES) {
            const float4* src = (const float4*)(g_cbT + cbase + TN);
            #pragma unroll
            for (int p = 0; p < 4; p++)
                pf[p] = __ldg(src + (p * 16 + dg) * (KCODES / 4) + jj);
        }

        // acc[rp][c]: rp=0 -> rows (0,1) packed, rp=1 -> rows (2,3) packed
        ull acc[2][4];
        #pragma unroll
        for (int rp = 0; rp < 2; rp++)
            #pragma unroll
            for (int c = 0; c < 4; c++) acc[rp][c] = 0ull;  // {0.f, 0.f}

        #pragma unroll 8
        for (int k = 0; k < DIM; k++) {
            const ull* zp = (const ull*)&zsT[k * ZS + rbase];
            ull z01 = zp[0];           // {z[row0], z[row1]}
            ull z23 = zp[1];           // {z[row2], z[row3]}
            float4 cv = *(const float4*)&csT[k * CS + cloc];
            ull c0 = pack2dup(cv.x);
            ull c1 = pack2dup(cv.y);
            ull c2 = pack2dup(cv.z);
            ull c3 = pack2dup(cv.w);
            fma2(acc[0][0], z01, c0); fma2(acc[1][0], z23, c0);
            fma2(acc[0][1], z01, c1); fma2(acc[1][1], z23, c1);
            fma2(acc[0][2], z01, c2); fma2(acc[1][2], z23, c2);
            fma2(acc[0][3], z01, c3); fma2(acc[1][3], z23, c3);
        }

        // epilogue: dist = fl( fl(znorm + cnorm) - fl(2*dot) ), codes ascending
        float4 cn4 = *(const float4*)(g_cnorm + cbase + cloc);
        float cna[4] = {cn4.x, cn4.y, cn4.z, cn4.w};
        #pragma unroll
        for (int c = 0; c < 4; c++) {
            int code = cbase + cloc + c;
            #pragma unroll
            for (int rp = 0; rp < 2; rp++) {
                float dlo, dhi;
                unpack2(acc[rp][c], dlo, dhi);
                int r0 = rp * 2, r1 = rp * 2 + 1;
                float t0 = __fadd_rn(zn[r0], cna[c]);
                float d0 = __fsub_rn(t0, __fmul_rn(2.0f, dlo));
                if (d0 < minval[r0]) { minval[r0] = d0; minidx[r0] = code; }
                float t1 = __fadd_rn(zn[r1], cna[c]);
                float d1 = __fsub_rn(t1, __fmul_rn(2.0f, dhi));
                if (d1 < minval[r1]) { minval[r1] = d1; minidx[r1] = code; }
            }
        }
        __syncthreads();
    }

    // ---- reduce over the 8 txl lanes (same tyl group) ----
    #pragma unroll
    for (int r = 0; r < 4; r++) {
        #pragma unroll
        for (int m = 4; m >= 1; m >>= 1) {
            float ov = __shfl_xor_sync(0xffffffffu, minval[r], m);
            int   oi = __shfl_xor_sync(0xffffffffu, minidx[r], m);
            if (ov < minval[r] || (ov == minval[r] && oi < minidx[r])) {
                minval[r] = ov; minidx[r] = oi;
            }
        }
    }

    // ---- cross-half combine: warps (w, w^1) share rows ----
    if (txl == 0) {
        #pragma unroll
        for (int r = 0; r < 4; r++) {
            mv_s[chalf][rbase + r] = minval[r];
            mi_s[chalf][rbase + r] = minidx[r];
        }
    }
    __syncthreads();

    if (tid < TM) {
        float v0 = mv_s[0][tid], v1 = mv_s[1][tid];
        int   i0 = mi_s[0][tid], i1 = mi_s[1][tid];
        // lexicographic (val, idx) min == first-min of the full ascending scan
        float v; int idx;
        if (v1 < v0 || (v1 == v0 && i1 < i0)) { v = v1; idx = i1; }
        else                                   { v = v0; idx = i0; }
        ridx_s[tid] = idx;
        lsum_v[tid] = v;                   // = ||z_row - c_idx||^2
        // write index (as float)
        out[NROWS * DIM + 1 + rowBase + tid] = (float)idx;
    }
    __syncthreads();

    // ---- fused loss: deterministic fixed-point atomic + ticket finalize ----
    if (tid == 0) {
        float s = 0.0f;
        #pragma unroll 8
        for (int i = 0; i < TM; i++) s = __fadd_rn(s, lsum_v[i]);
        ull q = (ull)__double2ll_rn((double)s * 1048576.0);
        atomicAdd(&g_loss_acc, q);
        __threadfence();
        unsigned int ticket = atomicAdd(&g_ticket, 1u);
        if (ticket == NBLOCKS - 1) {
            ull tot = atomicAdd(&g_loss_acc, 0ULL);   // coherent read
            double sum = (double)tot * (1.0 / 1048576.0);
            float mean = (float)(sum / (double)(NROWS * DIM));
            out[NROWS * DIM] = __fadd_rn(mean, __fmul_rn(0.25f, mean));
            g_loss_acc = 0ULL;     // reset for next graph replay
            g_ticket   = 0u;
            __threadfence();
        }
    }

    // ---- write z_q = codebook[idx] (coalesced) ----
    #pragma unroll
    for (int i = 0; i < 16; i++) {
        int flat = i * NTHREADS + tid;
        int r = flat >> 6, c = flat & 63;
        out[(rowBase + r) * DIM + c] = codebook[ridx_s[r] * DIM + c];
    }
}

extern "C" void kernel_launch(void* const* d_in, const int* in_sizes, int n_in,
                              void* d_out, int out_size) {
    const float* z        = (const float*)d_in[0];
    const float* codebook = (const float*)d_in[1];
    float* out = (float*)d_out;

    cnorm_kernel<<<KCODES / 64, 64>>>(codebook);
    vq_kernel<<<NBLOCKS, NTHREADS>>>(z, codebook, out);
}